// round 1
// baseline (speedup 1.0000x reference)
#include <cuda_runtime.h>
#include <math.h>

#define B_ 2
#define S_ 2048
#define D_ 1024
#define H_ 16
#define HD_ 64
#define EPS_ 1e-5f

// ---------------- scratch (static device globals; no allocation) ----------------
__device__ float g_h[B_ * S_ * D_];       // layernorm output
__device__ float g_q[B_ * S_ * D_];
__device__ float g_k[B_ * S_ * D_];
__device__ float g_v[B_ * S_ * D_];
__device__ float g_concat[B_ * S_ * D_];  // attention output, [B,S,H,HD] = [B,S,D]
__device__ float g_esum[B_ * H_ * S_];    // D_q = q + sum_{k>=q} exp(s[q,k])
__device__ float g_ediag[B_ * H_ * S_];   // exp(s[q,q])

// ---------------- LayerNorm: one block per row ----------------
__global__ void ln_kernel(const float* __restrict__ x,
                          const float* __restrict__ gamma,
                          const float* __restrict__ beta,
                          float* __restrict__ out) {
    const int row = blockIdx.x;           // B*S rows
    const int tid = threadIdx.x;          // 256 threads, 4 elems each
    const float* xr = x + (size_t)row * D_;

    float4 xv = ((const float4*)xr)[tid];
    float sum = xv.x + xv.y + xv.z + xv.w;
    float sq  = xv.x * xv.x + xv.y * xv.y + xv.z * xv.z + xv.w * xv.w;

    // block reduce (sum, sq) together
    __shared__ float2 red[32];
    float2 v2 = make_float2(sum, sq);
    #pragma unroll
    for (int o = 16; o > 0; o >>= 1) {
        v2.x += __shfl_down_sync(0xffffffffu, v2.x, o);
        v2.y += __shfl_down_sync(0xffffffffu, v2.y, o);
    }
    if ((tid & 31) == 0) red[tid >> 5] = v2;
    __syncthreads();
    if (tid < 32) {
        float2 w = (tid < 8) ? red[tid] : make_float2(0.f, 0.f);
        #pragma unroll
        for (int o = 4; o > 0; o >>= 1) {
            w.x += __shfl_down_sync(0xffffffffu, w.x, o);
            w.y += __shfl_down_sync(0xffffffffu, w.y, o);
        }
        if (tid == 0) red[0] = w;
    }
    __syncthreads();
    const float mu  = red[0].x * (1.0f / D_);
    const float var = red[0].y * (1.0f / D_) - mu * mu;
    const float inv = rsqrtf(var + EPS_);

    float4 g = ((const float4*)gamma)[tid];
    float4 b = ((const float4*)beta)[tid];
    float4 o;
    o.x = (xv.x - mu) * inv * g.x + b.x;
    o.y = (xv.y - mu) * inv * g.y + b.y;
    o.z = (xv.z - mu) * inv * g.z + b.z;
    o.w = (xv.w - mu) * inv * g.w + b.w;
    ((float4*)(out + (size_t)row * D_))[tid] = o;
}

// ---------------- SGEMM (NT): C[M,N] = A[M,K] @ W[N,K]^T + bias (+ res) ----------------
#define BM 128
#define BN 128
#define BK 8
__global__ __launch_bounds__(256) void sgemm_nt(const float* __restrict__ A,
                                                const float* __restrict__ W,
                                                const float* __restrict__ bias,
                                                const float* __restrict__ res,
                                                float* __restrict__ C,
                                                int M, int N, int K) {
    __shared__ float As[BK][BM];
    __shared__ float Ws[BK][BN];

    const int tid = threadIdx.x;
    const int bm = blockIdx.y * BM;
    const int bn = blockIdx.x * BN;

    const int lrow  = tid >> 1;            // 0..127
    const int lcol4 = (tid & 1) * 4;       // 0 or 4

    const int ty = tid >> 4;               // 0..15
    const int tx = tid & 15;               // 0..15

    float acc[8][8];
    #pragma unroll
    for (int i = 0; i < 8; i++)
        #pragma unroll
        for (int j = 0; j < 8; j++) acc[i][j] = 0.f;

    for (int k0 = 0; k0 < K; k0 += BK) {
        float4 av = *(const float4*)(A + (size_t)(bm + lrow) * K + k0 + lcol4);
        float4 wv = *(const float4*)(W + (size_t)(bn + lrow) * K + k0 + lcol4);
        As[lcol4 + 0][lrow] = av.x;
        As[lcol4 + 1][lrow] = av.y;
        As[lcol4 + 2][lrow] = av.z;
        As[lcol4 + 3][lrow] = av.w;
        Ws[lcol4 + 0][lrow] = wv.x;
        Ws[lcol4 + 1][lrow] = wv.y;
        Ws[lcol4 + 2][lrow] = wv.z;
        Ws[lcol4 + 3][lrow] = wv.w;
        __syncthreads();

        #pragma unroll
        for (int k = 0; k < BK; k++) {
            float ar[8], br[8];
            float4 a0 = *(const float4*)&As[k][ty * 8];
            float4 a1 = *(const float4*)&As[k][ty * 8 + 4];
            float4 b0 = *(const float4*)&Ws[k][tx * 8];
            float4 b1 = *(const float4*)&Ws[k][tx * 8 + 4];
            ar[0] = a0.x; ar[1] = a0.y; ar[2] = a0.z; ar[3] = a0.w;
            ar[4] = a1.x; ar[5] = a1.y; ar[6] = a1.z; ar[7] = a1.w;
            br[0] = b0.x; br[1] = b0.y; br[2] = b0.z; br[3] = b0.w;
            br[4] = b1.x; br[5] = b1.y; br[6] = b1.z; br[7] = b1.w;
            #pragma unroll
            for (int i = 0; i < 8; i++)
                #pragma unroll
                for (int j = 0; j < 8; j++) acc[i][j] += ar[i] * br[j];
        }
        __syncthreads();
    }

    #pragma unroll
    for (int i = 0; i < 8; i++) {
        const int m = bm + ty * 8 + i;
        #pragma unroll
        for (int j = 0; j < 8; j++) {
            const int n = bn + tx * 8 + j;
            float v = acc[i][j] + bias[n];
            if (res) v += res[(size_t)m * N + n];
            C[(size_t)m * N + n] = v;
        }
    }
}

// ---------------- scores: per-row exp-sum over upper triangle + diag ----------------
// block: 128 threads, each owns one q row. grid: (S/128, B*H)
__global__ __launch_bounds__(128) void scores_kernel(const float* __restrict__ Q,
                                                     const float* __restrict__ Kmat,
                                                     float* __restrict__ esum,
                                                     float* __restrict__ ediag) {
    const int q0 = blockIdx.x * 128;
    const int bh = blockIdx.y;
    const int b  = bh / H_;
    const int hh = bh % H_;
    const int tid = threadIdx.x;
    const int q = q0 + tid;

    __shared__ float Ks[64][65];

    // load my Q row into registers
    float qreg[64];
    const float4* qp = (const float4*)(Q + ((size_t)(b * S_ + q)) * D_ + hh * HD_);
    #pragma unroll
    for (int i = 0; i < 16; i++) {
        float4 t4 = qp[i];
        qreg[4 * i + 0] = t4.x;
        qreg[4 * i + 1] = t4.y;
        qreg[4 * i + 2] = t4.z;
        qreg[4 * i + 3] = t4.w;
    }

    float acc = 0.f, ed = 0.f;
    const float scale = 0.03125f;  // 1/sqrt(1024)

    for (int kt = q0; kt < S_; kt += 64) {
        __syncthreads();
        // cooperative load of 64x64 K tile (float4 granularity)
        #pragma unroll
        for (int i = tid; i < 64 * 16; i += 128) {
            const int row = i >> 4, c4 = (i & 15) * 4;
            float4 t4 = *(const float4*)(Kmat + ((size_t)(b * S_ + kt + row)) * D_ + hh * HD_ + c4);
            Ks[row][c4 + 0] = t4.x;
            Ks[row][c4 + 1] = t4.y;
            Ks[row][c4 + 2] = t4.z;
            Ks[row][c4 + 3] = t4.w;
        }
        __syncthreads();

        #pragma unroll 2
        for (int kk = 0; kk < 64; kk++) {
            const int kg = kt + kk;
            float s = 0.f;
            #pragma unroll
            for (int d = 0; d < 64; d++) s += qreg[d] * Ks[kk][d];
            s *= scale;
            if (kg >= q) {
                const float e = __expf(s);
                acc += e;
                if (kg == q) ed = e;
            }
        }
    }

    esum[bh * S_ + q]  = (float)q + acc;  // q zeros below diagonal contribute exp(0)=1 each
    ediag[bh * S_ + q] = ed;
}

// ---------------- attention output: prefix-sum of V per head + scale ----------------
// grid: B*H blocks; block: 1024 threads = 16 s-tiles x 64 dims
__global__ __launch_bounds__(1024) void attnout_kernel(const float* __restrict__ V,
                                                       const float* __restrict__ esum,
                                                       const float* __restrict__ ediag,
                                                       float* __restrict__ out) {
    const int bh = blockIdx.x;
    const int b  = bh / H_;
    const int hh = bh % H_;
    const int tid = threadIdx.x;
    const int t = tid >> 6;    // 0..15 tile
    const int d = tid & 63;    // 0..63 dim

    __shared__ float tileSum[16][64];

    const size_t base = ((size_t)b * S_) * D_ + hh * HD_ + d;
    const int s0 = t * 128;

    float s = 0.f;
    for (int i = 0; i < 128; i++) s += V[base + (size_t)(s0 + i) * D_];
    tileSum[t][d] = s;
    __syncthreads();

    float run = 0.f;
    for (int tt = 0; tt < t; tt++) run += tileSum[tt][d];

    for (int i = 0; i < 128; i++) {
        const int q = s0 + i;
        const float val = V[base + (size_t)q * D_];
        const float e   = ediag[bh * S_ + q];
        const float Dn  = esum[bh * S_ + q];
        out[base + (size_t)q * D_] = (run + e * val) / Dn;
        run += val;
    }
}

// ---------------- launch ----------------
extern "C" void kernel_launch(void* const* d_in, const int* in_sizes, int n_in,
                              void* d_out, int out_size) {
    const float* x     = (const float*)d_in[0];
    const float* wq    = (const float*)d_in[1];
    const float* bq    = (const float*)d_in[2];
    const float* wk    = (const float*)d_in[3];
    const float* bk    = (const float*)d_in[4];
    const float* wv    = (const float*)d_in[5];
    const float* bv    = (const float*)d_in[6];
    const float* wo    = (const float*)d_in[7];
    const float* bo    = (const float*)d_in[8];
    const float* gamma = (const float*)d_in[9];
    const float* beta  = (const float*)d_in[10];
    float* out = (float*)d_out;

    float *hbuf, *qbuf, *kbuf, *vbuf, *cbuf, *esum, *ediag;
    cudaGetSymbolAddress((void**)&hbuf,  g_h);
    cudaGetSymbolAddress((void**)&qbuf,  g_q);
    cudaGetSymbolAddress((void**)&kbuf,  g_k);
    cudaGetSymbolAddress((void**)&vbuf,  g_v);
    cudaGetSymbolAddress((void**)&cbuf,  g_concat);
    cudaGetSymbolAddress((void**)&esum,  g_esum);
    cudaGetSymbolAddress((void**)&ediag, g_ediag);

    const int M = B_ * S_;  // 4096

    // 1) LayerNorm
    ln_kernel<<<M, 256>>>(x, gamma, beta, hbuf);

    // 2) Q/K/V projections
    dim3 gg(D_ / BN, M / BM);
    sgemm_nt<<<gg, 256>>>(hbuf, wq, bq, nullptr, qbuf, M, D_, D_);
    sgemm_nt<<<gg, 256>>>(hbuf, wk, bk, nullptr, kbuf, M, D_, D_);
    sgemm_nt<<<gg, 256>>>(hbuf, wv, bv, nullptr, vbuf, M, D_, D_);

    // 3) scores -> per-row exp-sum + diag
    dim3 gs(S_ / 128, B_ * H_);
    scores_kernel<<<gs, 128>>>(qbuf, kbuf, esum, ediag);

    // 4) attention output via V prefix sums
    attnout_kernel<<<B_ * H_, 1024>>>(vbuf, esum, ediag, cbuf);

    // 5) output projection + residual
    sgemm_nt<<<gg, 256>>>(cbuf, wo, bo, x, out, M, D_, D_);
}

// round 3
// speedup vs baseline: 1.8648x; 1.8648x over previous
#include <cuda_runtime.h>
#include <math.h>
#include <cstdint>

#define B_ 2
#define S_ 2048
#define D_ 1024
#define H_ 16
#define HD_ 64
#define EPS_ 1e-5f

// ---------------- scratch ----------------
__device__ float g_h[B_ * S_ * D_];
__device__ float g_q[B_ * S_ * D_];
__device__ float g_k[B_ * S_ * D_];
__device__ float g_v[B_ * S_ * D_];
__device__ float g_concat[B_ * S_ * D_];
__device__ float g_esum[B_ * H_ * S_];
__device__ float g_ediag[B_ * H_ * S_];
__device__ float g_tsum[B_ * H_ * 16 * HD_];
__device__ float g_wqr[D_ * D_];
__device__ float g_wkr[D_ * D_];
__device__ float g_wvr[D_ * D_];
__device__ float g_wor[D_ * D_];

// ---------------- helpers ----------------
__device__ __forceinline__ uint32_t smem_u32(const void* p) {
    uint32_t a;
    asm("{ .reg .u64 t; cvta.to.shared.u64 t, %1; cvt.u32.u64 %0, t; }" : "=r"(a) : "l"(p));
    return a;
}
__device__ __forceinline__ float to_tf32(float x) {
    uint32_t r;
    asm("cvt.rna.tf32.f32 %0, %1;" : "=r"(r) : "f"(x));
    return __uint_as_float(r);
}
__device__ __forceinline__ void cp_async16(uint32_t dst, const void* src) {
    asm volatile("cp.async.cg.shared.global [%0], [%1], 16;" :: "r"(dst), "l"(src));
}
#define CP_COMMIT() asm volatile("cp.async.commit_group;" ::: "memory")

__device__ __forceinline__ void mma_tf32(float c[4], const uint32_t a[4], const uint32_t b[2]) {
    asm volatile(
        "mma.sync.aligned.m16n8k8.row.col.f32.tf32.tf32.f32 "
        "{%0,%1,%2,%3}, {%4,%5,%6,%7}, {%8,%9}, {%0,%1,%2,%3};"
        : "+f"(c[0]), "+f"(c[1]), "+f"(c[2]), "+f"(c[3])
        : "r"(a[0]), "r"(a[1]), "r"(a[2]), "r"(a[3]), "r"(b[0]), "r"(b[1]));
}

// ================= tf32 mma.sync GEMM =================
// C[4096,1024] = A[4096,1024] @ W[1024,1024]^T + bias (+res)
// 128x128x32 block tile, 3-stage cp.async, 8 warps (64x32 warp tiles).
#define GK       1024
#define GN       1024
#define G_STAGEF 4096          // floats per matrix stage (128 rows * 32)
#define G_SMEMB  (3 * G_STAGEF * 4 * 2)   // 96 KB

__device__ __forceinline__ void g_load_stage(uint32_t sbase, const float* A, const float* W,
                                             int bm, int bn, int it, int slot, int tid) {
    const int k0 = it * 32;
    const uint32_t abase = sbase + slot * (G_STAGEF * 4);
    const uint32_t bbase = sbase + (3 + slot) * (G_STAGEF * 4);
    #pragma unroll
    for (int i = 0; i < 4; i++) {
        const int c = tid + i * 256;      // 0..1023 chunk id
        const int row = c >> 3;
        const int c4 = c & 7;
        const uint32_t off = (uint32_t)(row * 128 + (((c4 << 4)) ^ ((row & 7) << 4)));
        cp_async16(abase + off, A + (size_t)(bm + row) * GK + k0 + (c4 << 2));
        cp_async16(bbase + off, W + (size_t)(bn + row) * GK + k0 + (c4 << 2));
    }
    CP_COMMIT();
}

__global__ __launch_bounds__(256, 2) void gemm_mma(const float* __restrict__ A,
                                                   const float* __restrict__ W,
                                                   const float* __restrict__ bias,
                                                   const float* __restrict__ res,
                                                   float* __restrict__ C) {
    extern __shared__ float smf[];
    const uint32_t sbase = smem_u32(smf);
    const int tid = threadIdx.x;
    const int wid = tid >> 5, lane = tid & 31;
    const int g = lane >> 2, tg = lane & 3;
    const int wm = (wid & 1) * 64, wn = (wid >> 1) * 32;
    const int bm = blockIdx.y * 128, bn = blockIdx.x * 128;

    float acc[4][4][4];
    #pragma unroll
    for (int i = 0; i < 4; i++)
        #pragma unroll
        for (int j = 0; j < 4; j++)
            #pragma unroll
            for (int e = 0; e < 4; e++) acc[i][j][e] = 0.f;

    g_load_stage(sbase, A, W, bm, bn, 0, 0, tid);
    g_load_stage(sbase, A, W, bm, bn, 1, 1, tid);

    const int nIter = GK / 32;  // 32
    for (int it = 0; it < nIter; it++) {
        const int slot = it % 3;
        if (it < nIter - 1) {
            asm volatile("cp.async.wait_group 1;" ::: "memory");
        } else {
            asm volatile("cp.async.wait_group 0;" ::: "memory");
        }
        __syncthreads();
        if (it + 2 < nIter) g_load_stage(sbase, A, W, bm, bn, it + 2, (it + 2) % 3, tid);

        const uint32_t* asu = (const uint32_t*)(smf + slot * G_STAGEF);
        const uint32_t* bsu = (const uint32_t*)(smf + (3 + slot) * G_STAGEF);

        #pragma unroll
        for (int ks = 0; ks < 4; ks++) {
            const int k8 = ks * 8;
            const int c0 = (k8 + tg) ^ (g << 2);
            const int c1 = (k8 + tg + 4) ^ (g << 2);
            uint32_t af[4][4], bf[4][2];
            #pragma unroll
            for (int i = 0; i < 4; i++) {
                const int row = wm + i * 16 + g;
                af[i][0] = asu[row * 32 + c0];
                af[i][1] = asu[(row + 8) * 32 + c0];
                af[i][2] = asu[row * 32 + c1];
                af[i][3] = asu[(row + 8) * 32 + c1];
            }
            #pragma unroll
            for (int j = 0; j < 4; j++) {
                const int n = wn + j * 8 + g;
                bf[j][0] = bsu[n * 32 + c0];
                bf[j][1] = bsu[n * 32 + c1];
            }
            #pragma unroll
            for (int i = 0; i < 4; i++)
                #pragma unroll
                for (int j = 0; j < 4; j++) mma_tf32(acc[i][j], af[i], bf[j]);
        }
    }

    // epilogue
    #pragma unroll
    for (int i = 0; i < 4; i++) {
        const int row = bm + wm + i * 16 + g;
        #pragma unroll
        for (int j = 0; j < 4; j++) {
            const int col = bn + wn + j * 8 + tg * 2;
            const float2 bv = *(const float2*)(bias + col);
            float2 o0, o1;
            o0.x = acc[i][j][0] + bv.x;  o0.y = acc[i][j][1] + bv.y;
            o1.x = acc[i][j][2] + bv.x;  o1.y = acc[i][j][3] + bv.y;
            if (res) {
                const float2 r0 = *(const float2*)(res + (size_t)row * GN + col);
                const float2 r1 = *(const float2*)(res + (size_t)(row + 8) * GN + col);
                o0.x += r0.x; o0.y += r0.y;
                o1.x += r1.x; o1.y += r1.y;
            }
            *(float2*)(C + (size_t)row * GN + col) = o0;
            *(float2*)(C + (size_t)(row + 8) * GN + col) = o1;
        }
    }
}

// ---------------- weight rounding to tf32 ----------------
__global__ void tf32_round_kernel(const float* __restrict__ in, float* __restrict__ out) {
    const int i = blockIdx.x * blockDim.x + threadIdx.x;  // float4 index
    float4 v = ((const float4*)in)[i];
    v.x = to_tf32(v.x); v.y = to_tf32(v.y); v.z = to_tf32(v.z); v.w = to_tf32(v.w);
    ((float4*)out)[i] = v;
}

// ---------------- LayerNorm (output rounded to tf32) ----------------
__global__ void ln_kernel(const float* __restrict__ x,
                          const float* __restrict__ gamma,
                          const float* __restrict__ beta,
                          float* __restrict__ out) {
    const int row = blockIdx.x;
    const int tid = threadIdx.x;
    const float* xr = x + (size_t)row * D_;

    float4 xv = ((const float4*)xr)[tid];
    float sum = xv.x + xv.y + xv.z + xv.w;
    float sq  = xv.x * xv.x + xv.y * xv.y + xv.z * xv.z + xv.w * xv.w;

    __shared__ float2 red[32];
    float2 v2 = make_float2(sum, sq);
    #pragma unroll
    for (int o = 16; o > 0; o >>= 1) {
        v2.x += __shfl_down_sync(0xffffffffu, v2.x, o);
        v2.y += __shfl_down_sync(0xffffffffu, v2.y, o);
    }
    if ((tid & 31) == 0) red[tid >> 5] = v2;
    __syncthreads();
    if (tid < 32) {
        float2 w = (tid < 8) ? red[tid] : make_float2(0.f, 0.f);
        #pragma unroll
        for (int o = 4; o > 0; o >>= 1) {
            w.x += __shfl_down_sync(0xffffffffu, w.x, o);
            w.y += __shfl_down_sync(0xffffffffu, w.y, o);
        }
        if (tid == 0) red[0] = w;
    }
    __syncthreads();
    const float mu  = red[0].x * (1.0f / D_);
    const float var = red[0].y * (1.0f / D_) - mu * mu;
    const float inv = rsqrtf(var + EPS_);

    float4 gm = ((const float4*)gamma)[tid];
    float4 b = ((const float4*)beta)[tid];
    float4 o;
    o.x = to_tf32((xv.x - mu) * inv * gm.x + b.x);
    o.y = to_tf32((xv.y - mu) * inv * gm.y + b.y);
    o.z = to_tf32((xv.z - mu) * inv * gm.z + b.z);
    o.w = to_tf32((xv.w - mu) * inv * gm.w + b.w);
    ((float4*)(out + (size_t)row * D_))[tid] = o;
}

// ---------------- scores: exp-rowsums over upper triangle ----------------
__global__ __launch_bounds__(128) void scores_kernel(const float* __restrict__ Q,
                                                     const float* __restrict__ Kmat,
                                                     float* __restrict__ esum,
                                                     float* __restrict__ ediag) {
    const int q0 = blockIdx.x * 128;
    const int bh = blockIdx.y;
    const int b  = bh / H_;
    const int hh = bh % H_;
    const int tid = threadIdx.x;
    const int q = q0 + tid;

    __shared__ float Ks[64][68];

    float4 qreg[16];
    const float4* qp = (const float4*)(Q + ((size_t)(b * S_ + q)) * D_ + hh * HD_);
    #pragma unroll
    for (int i = 0; i < 16; i++) qreg[i] = qp[i];

    float acc = 0.f, ed = 0.f;
    const float scale = 0.03125f;  // 1/sqrt(1024)

    for (int kt = q0; kt < S_; kt += 64) {
        __syncthreads();
        #pragma unroll
        for (int i = tid; i < 64 * 16; i += 128) {
            const int row = i >> 4, c4 = (i & 15) * 4;
            float4 t4 = *(const float4*)(Kmat + ((size_t)(b * S_ + kt + row)) * D_ + hh * HD_ + c4);
            *(float4*)&Ks[row][c4] = t4;
        }
        __syncthreads();

        #pragma unroll 2
        for (int kk = 0; kk < 64; kk++) {
            const int kg = kt + kk;
            float s = 0.f;
            #pragma unroll
            for (int d4 = 0; d4 < 16; d4++) {
                const float4 kv = *(const float4*)&Ks[kk][d4 * 4];
                s += qreg[d4].x * kv.x + qreg[d4].y * kv.y
                   + qreg[d4].z * kv.z + qreg[d4].w * kv.w;
            }
            s *= scale;
            if (kg >= q) {
                const float e = __expf(s);
                acc += e;
                if (kg == q) ed = e;
            }
        }
    }

    esum[bh * S_ + q]  = (float)q + acc;
    ediag[bh * S_ + q] = ed;
}

// ---------------- attention output: tile sums then prefix ----------------
__global__ __launch_bounds__(128) void tilesum_kernel(const float* __restrict__ V,
                                                      float* __restrict__ tsum) {
    const int t  = blockIdx.x;       // 0..15
    const int bh = blockIdx.y;       // 0..31
    const int b  = bh / H_;
    const int hh = bh % H_;
    const int d = threadIdx.x & 63;
    const int half = threadIdx.x >> 6;

    const size_t base = ((size_t)b * S_) * D_ + hh * HD_ + d;
    const int s0 = t * 128 + half * 64;
    float s = 0.f;
    for (int i = 0; i < 64; i++) s += V[base + (size_t)(s0 + i) * D_];

    __shared__ float sh[64];
    if (half == 0) sh[d] = s;
    __syncthreads();
    if (half == 1) tsum[(bh * 16 + t) * 64 + d] = sh[d] + s;
}

__global__ __launch_bounds__(64) void attnout_kernel(const float* __restrict__ V,
                                                     const float* __restrict__ tsum,
                                                     const float* __restrict__ esum,
                                                     const float* __restrict__ ediag,
                                                     float* __restrict__ out) {
    const int t  = blockIdx.x;
    const int bh = blockIdx.y;
    const int b  = bh / H_;
    const int hh = bh % H_;
    const int d = threadIdx.x;

    const size_t base = ((size_t)b * S_) * D_ + hh * HD_ + d;

    float run = 0.f;
    for (int tt = 0; tt < t; tt++) run += tsum[(bh * 16 + tt) * 64 + d];

    const int s0 = t * 128;
    for (int i = 0; i < 128; i++) {
        const int q = s0 + i;
        const float val = V[base + (size_t)q * D_];
        const float e   = ediag[bh * S_ + q];
        const float Dn  = esum[bh * S_ + q];
        out[base + (size_t)q * D_] = to_tf32((run + e * val) / Dn);
        run += val;
    }
}

// ---------------- launch ----------------
extern "C" void kernel_launch(void* const* d_in, const int* in_sizes, int n_in,
                              void* d_out, int out_size) {
    const float* x     = (const float*)d_in[0];
    const float* wq    = (const float*)d_in[1];
    const float* bq    = (const float*)d_in[2];
    const float* wk    = (const float*)d_in[3];
    const float* bk    = (const float*)d_in[4];
    const float* wv    = (const float*)d_in[5];
    const float* bv    = (const float*)d_in[6];
    const float* wo    = (const float*)d_in[7];
    const float* bo    = (const float*)d_in[8];
    const float* gamma = (const float*)d_in[9];
    const float* beta  = (const float*)d_in[10];
    float* out = (float*)d_out;

    float *hbuf, *qbuf, *kbuf, *vbuf, *cbuf, *esum, *ediag, *tsum;
    float *wqr, *wkr, *wvr, *wor;
    cudaGetSymbolAddress((void**)&hbuf,  g_h);
    cudaGetSymbolAddress((void**)&qbuf,  g_q);
    cudaGetSymbolAddress((void**)&kbuf,  g_k);
    cudaGetSymbolAddress((void**)&vbuf,  g_v);
    cudaGetSymbolAddress((void**)&cbuf,  g_concat);
    cudaGetSymbolAddress((void**)&esum,  g_esum);
    cudaGetSymbolAddress((void**)&ediag, g_ediag);
    cudaGetSymbolAddress((void**)&tsum,  g_tsum);
    cudaGetSymbolAddress((void**)&wqr,   g_wqr);
    cudaGetSymbolAddress((void**)&wkr,   g_wkr);
    cudaGetSymbolAddress((void**)&wvr,   g_wvr);
    cudaGetSymbolAddress((void**)&wor,   g_wor);

    cudaFuncSetAttribute(gemm_mma, cudaFuncAttributeMaxDynamicSharedMemorySize, G_SMEMB);

    const int M = B_ * S_;  // 4096

    // round weights to tf32 (unbiased)
    const int rblocks = (D_ * D_ / 4) / 256;  // 1024
    tf32_round_kernel<<<rblocks, 256>>>(wq, wqr);
    tf32_round_kernel<<<rblocks, 256>>>(wk, wkr);
    tf32_round_kernel<<<rblocks, 256>>>(wv, wvr);
    tf32_round_kernel<<<rblocks, 256>>>(wo, wor);

    ln_kernel<<<M, 256>>>(x, gamma, beta, hbuf);

    dim3 gg(D_ / 128, M / 128);  // (8, 32)
    gemm_mma<<<gg, 256, G_SMEMB>>>(hbuf, wqr, bq, nullptr, qbuf);
    gemm_mma<<<gg, 256, G_SMEMB>>>(hbuf, wkr, bk, nullptr, kbuf);
    gemm_mma<<<gg, 256, G_SMEMB>>>(hbuf, wvr, bv, nullptr, vbuf);

    dim3 gs(S_ / 128, B_ * H_);
    scores_kernel<<<gs, 128>>>(qbuf, kbuf, esum, ediag);

    dim3 ga(16, B_ * H_);
    tilesum_kernel<<<ga, 128>>>(vbuf, tsum);
    attnout_kernel<<<ga, 64>>>(vbuf, tsum, esum, ediag, cbuf);

    gemm_mma<<<gg, 256, G_SMEMB>>>(cbuf, wor, bo, x, out);
}

// round 4
// speedup vs baseline: 5.6537x; 3.0319x over previous
#include <cuda_runtime.h>
#include <cuda_bf16.h>
#include <math.h>
#include <cstdint>

#define B_ 2
#define S_ 2048
#define D_ 1024
#define H_ 16
#define HD_ 64
#define EPS_ 1e-5f

// ---------------- scratch ----------------
__device__ __nv_bfloat16 g_hb[B_ * S_ * D_];    // layernorm out (bf16)
__device__ __nv_bfloat16 g_qb[B_ * S_ * D_];
__device__ __nv_bfloat16 g_kb[B_ * S_ * D_];
__device__ float         g_v[B_ * S_ * D_];
__device__ float         g_concat[B_ * S_ * D_];  // tf32-rounded
__device__ float         g_esum[B_ * H_ * S_];
__device__ float         g_ediag[B_ * H_ * S_];
__device__ float         g_tsum[B_ * H_ * 32 * HD_];
__device__ __nv_bfloat16 g_wqb[D_ * D_];
__device__ __nv_bfloat16 g_wkb[D_ * D_];
__device__ __nv_bfloat16 g_wvb[D_ * D_];
__device__ float         g_wor[D_ * D_];          // tf32-rounded

// ---------------- helpers ----------------
__device__ __forceinline__ uint32_t smem_u32(const void* p) {
    uint32_t a;
    asm("{ .reg .u64 t; cvta.to.shared.u64 t, %1; cvt.u32.u64 %0, t; }" : "=r"(a) : "l"(p));
    return a;
}
__device__ __forceinline__ float to_tf32(float x) {
    uint32_t r;
    asm("cvt.rna.tf32.f32 %0, %1;" : "=r"(r) : "f"(x));
    return __uint_as_float(r);
}
__device__ __forceinline__ void cp_async16(uint32_t dst, const void* src) {
    asm volatile("cp.async.cg.shared.global [%0], [%1], 16;" :: "r"(dst), "l"(src));
}
#define CP_COMMIT() asm volatile("cp.async.commit_group;" ::: "memory")

__device__ __forceinline__ void mma_tf32(float c[4], const uint32_t a[4], const uint32_t b[2]) {
    asm volatile(
        "mma.sync.aligned.m16n8k8.row.col.f32.tf32.tf32.f32 "
        "{%0,%1,%2,%3}, {%4,%5,%6,%7}, {%8,%9}, {%0,%1,%2,%3};"
        : "+f"(c[0]), "+f"(c[1]), "+f"(c[2]), "+f"(c[3])
        : "r"(a[0]), "r"(a[1]), "r"(a[2]), "r"(a[3]), "r"(b[0]), "r"(b[1]));
}
__device__ __forceinline__ void mma_bf16(float c[4], const uint32_t a[4], const uint32_t b[2]) {
    asm volatile(
        "mma.sync.aligned.m16n8k16.row.col.f32.bf16.bf16.f32 "
        "{%0,%1,%2,%3}, {%4,%5,%6,%7}, {%8,%9}, {%0,%1,%2,%3};"
        : "+f"(c[0]), "+f"(c[1]), "+f"(c[2]), "+f"(c[3])
        : "r"(a[0]), "r"(a[1]), "r"(a[2]), "r"(a[3]), "r"(b[0]), "r"(b[1]));
}

// ================= bf16 mma GEMM =================
// C[4096,1024] = A[4096,1024]bf16 @ W[1024,1024]bf16^T + bias
// 128x128x64 tile, 3-stage cp.async, 8 warps. Stage: 128 rows * 64 bf16 = 16KB.
#define BG_STAGEB 16384
#define BG_SMEMB  (3 * BG_STAGEB * 2)   // 96 KB

__device__ __forceinline__ void bg_load_stage(uint32_t sbase, const __nv_bfloat16* A,
                                              const __nv_bfloat16* W,
                                              int bm, int bn, int it, int slot, int tid) {
    const int k0 = it * 64;
    const uint32_t abase = sbase + slot * BG_STAGEB;
    const uint32_t bbase = sbase + (3 + slot) * BG_STAGEB;
    #pragma unroll
    for (int i = 0; i < 4; i++) {
        const int c = tid + i * 256;  // 0..1023 chunk id
        const int row = c >> 3;
        const int c4 = c & 7;
        const uint32_t off = (uint32_t)(row * 128 + ((c4 ^ (row & 7)) << 4));
        cp_async16(abase + off, A + (size_t)(bm + row) * D_ + k0 + c4 * 8);
        cp_async16(bbase + off, W + (size_t)(bn + row) * D_ + k0 + c4 * 8);
    }
    CP_COMMIT();
}

__global__ __launch_bounds__(256, 2) void gemm_bf16(const __nv_bfloat16* __restrict__ A,
                                                    const __nv_bfloat16* __restrict__ W,
                                                    const float* __restrict__ bias,
                                                    __nv_bfloat16* __restrict__ Cb,
                                                    float* __restrict__ Cf) {
    extern __shared__ char smc[];
    const uint32_t sbase = smem_u32(smc);
    const uint32_t* su = (const uint32_t*)smc;   // bf16-pair view, row stride 32
    const int tid = threadIdx.x;
    const int wid = tid >> 5, lane = tid & 31;
    const int g = lane >> 2, tg = lane & 3;
    const int wm = (wid & 1) * 64, wn = (wid >> 1) * 32;
    const int bm = blockIdx.y * 128, bn = blockIdx.x * 128;

    float acc[4][4][4];
    #pragma unroll
    for (int i = 0; i < 4; i++)
        #pragma unroll
        for (int j = 0; j < 4; j++)
            #pragma unroll
            for (int e = 0; e < 4; e++) acc[i][j][e] = 0.f;

    bg_load_stage(sbase, A, W, bm, bn, 0, 0, tid);
    bg_load_stage(sbase, A, W, bm, bn, 1, 1, tid);

    const int nIter = D_ / 64;  // 16
    for (int it = 0; it < nIter; it++) {
        const int slot = it % 3;
        if (it < nIter - 1) {
            asm volatile("cp.async.wait_group 1;" ::: "memory");
        } else {
            asm volatile("cp.async.wait_group 0;" ::: "memory");
        }
        __syncthreads();
        if (it + 2 < nIter) bg_load_stage(sbase, A, W, bm, bn, it + 2, (it + 2) % 3, tid);

        const uint32_t* asu = su + slot * 4096;
        const uint32_t* bsu = su + (3 + slot) * 4096;

        #pragma unroll
        for (int ks = 0; ks < 4; ks++) {
            const int p0 = (ks * 8 + tg) ^ (g << 2);
            const int p1 = (ks * 8 + 4 + tg) ^ (g << 2);
            uint32_t af[4][4], bf[4][2];
            #pragma unroll
            for (int i = 0; i < 4; i++) {
                const int row = wm + i * 16 + g;
                af[i][0] = asu[row * 32 + p0];
                af[i][1] = asu[(row + 8) * 32 + p0];
                af[i][2] = asu[row * 32 + p1];
                af[i][3] = asu[(row + 8) * 32 + p1];
            }
            #pragma unroll
            for (int j = 0; j < 4; j++) {
                const int n = wn + j * 8 + g;
                bf[j][0] = bsu[n * 32 + p0];
                bf[j][1] = bsu[n * 32 + p1];
            }
            #pragma unroll
            for (int i = 0; i < 4; i++)
                #pragma unroll
                for (int j = 0; j < 4; j++) mma_bf16(acc[i][j], af[i], bf[j]);
        }
    }

    // epilogue
    #pragma unroll
    for (int i = 0; i < 4; i++) {
        const int row = bm + wm + i * 16 + g;
        #pragma unroll
        for (int j = 0; j < 4; j++) {
            const int col = bn + wn + j * 8 + tg * 2;
            const float2 bv = *(const float2*)(bias + col);
            float o00 = acc[i][j][0] + bv.x, o01 = acc[i][j][1] + bv.y;
            float o10 = acc[i][j][2] + bv.x, o11 = acc[i][j][3] + bv.y;
            if (Cb) {
                __nv_bfloat162 h0, h1;
                h0.x = __float2bfloat16(o00); h0.y = __float2bfloat16(o01);
                h1.x = __float2bfloat16(o10); h1.y = __float2bfloat16(o11);
                *(__nv_bfloat162*)(Cb + (size_t)row * D_ + col) = h0;
                *(__nv_bfloat162*)(Cb + (size_t)(row + 8) * D_ + col) = h1;
            } else {
                *(float2*)(Cf + (size_t)row * D_ + col) = make_float2(o00, o01);
                *(float2*)(Cf + (size_t)(row + 8) * D_ + col) = make_float2(o10, o11);
            }
        }
    }
}

// ================= tf32 mma GEMM (output projection) =================
#define GK       1024
#define GN       1024
#define G_STAGEF 4096
#define G_SMEMB  (3 * G_STAGEF * 4 * 2)   // 96 KB

__device__ __forceinline__ void g_load_stage(uint32_t sbase, const float* A, const float* W,
                                             int bm, int bn, int it, int slot, int tid) {
    const int k0 = it * 32;
    const uint32_t abase = sbase + slot * (G_STAGEF * 4);
    const uint32_t bbase = sbase + (3 + slot) * (G_STAGEF * 4);
    #pragma unroll
    for (int i = 0; i < 4; i++) {
        const int c = tid + i * 256;
        const int row = c >> 3;
        const int c4 = c & 7;
        const uint32_t off = (uint32_t)(row * 128 + (((c4 << 4)) ^ ((row & 7) << 4)));
        cp_async16(abase + off, A + (size_t)(bm + row) * GK + k0 + (c4 << 2));
        cp_async16(bbase + off, W + (size_t)(bn + row) * GK + k0 + (c4 << 2));
    }
    CP_COMMIT();
}

__global__ __launch_bounds__(256, 2) void gemm_mma(const float* __restrict__ A,
                                                   const float* __restrict__ W,
                                                   const float* __restrict__ bias,
                                                   const float* __restrict__ res,
                                                   float* __restrict__ C) {
    extern __shared__ float smf[];
    const uint32_t sbase = smem_u32(smf);
    const int tid = threadIdx.x;
    const int wid = tid >> 5, lane = tid & 31;
    const int g = lane >> 2, tg = lane & 3;
    const int wm = (wid & 1) * 64, wn = (wid >> 1) * 32;
    const int bm = blockIdx.y * 128, bn = blockIdx.x * 128;

    float acc[4][4][4];
    #pragma unroll
    for (int i = 0; i < 4; i++)
        #pragma unroll
        for (int j = 0; j < 4; j++)
            #pragma unroll
            for (int e = 0; e < 4; e++) acc[i][j][e] = 0.f;

    g_load_stage(sbase, A, W, bm, bn, 0, 0, tid);
    g_load_stage(sbase, A, W, bm, bn, 1, 1, tid);

    const int nIter = GK / 32;
    for (int it = 0; it < nIter; it++) {
        const int slot = it % 3;
        if (it < nIter - 1) {
            asm volatile("cp.async.wait_group 1;" ::: "memory");
        } else {
            asm volatile("cp.async.wait_group 0;" ::: "memory");
        }
        __syncthreads();
        if (it + 2 < nIter) g_load_stage(sbase, A, W, bm, bn, it + 2, (it + 2) % 3, tid);

        const uint32_t* asu = (const uint32_t*)(smf + slot * G_STAGEF);
        const uint32_t* bsu = (const uint32_t*)(smf + (3 + slot) * G_STAGEF);

        #pragma unroll
        for (int ks = 0; ks < 4; ks++) {
            const int k8 = ks * 8;
            const int c0 = (k8 + tg) ^ (g << 2);
            const int c1 = (k8 + tg + 4) ^ (g << 2);
            uint32_t af[4][4], bf[4][2];
            #pragma unroll
            for (int i = 0; i < 4; i++) {
                const int row = wm + i * 16 + g;
                af[i][0] = asu[row * 32 + c0];
                af[i][1] = asu[(row + 8) * 32 + c0];
                af[i][2] = asu[row * 32 + c1];
                af[i][3] = asu[(row + 8) * 32 + c1];
            }
            #pragma unroll
            for (int j = 0; j < 4; j++) {
                const int n = wn + j * 8 + g;
                bf[j][0] = bsu[n * 32 + c0];
                bf[j][1] = bsu[n * 32 + c1];
            }
            #pragma unroll
            for (int i = 0; i < 4; i++)
                #pragma unroll
                for (int j = 0; j < 4; j++) mma_tf32(acc[i][j], af[i], bf[j]);
        }
    }

    #pragma unroll
    for (int i = 0; i < 4; i++) {
        const int row = bm + wm + i * 16 + g;
        #pragma unroll
        for (int j = 0; j < 4; j++) {
            const int col = bn + wn + j * 8 + tg * 2;
            const float2 bv = *(const float2*)(bias + col);
            float2 o0, o1;
            o0.x = acc[i][j][0] + bv.x;  o0.y = acc[i][j][1] + bv.y;
            o1.x = acc[i][j][2] + bv.x;  o1.y = acc[i][j][3] + bv.y;
            if (res) {
                const float2 r0 = *(const float2*)(res + (size_t)row * GN + col);
                const float2 r1 = *(const float2*)(res + (size_t)(row + 8) * GN + col);
                o0.x += r0.x; o0.y += r0.y;
                o1.x += r1.x; o1.y += r1.y;
            }
            *(float2*)(C + (size_t)row * GN + col) = o0;
            *(float2*)(C + (size_t)(row + 8) * GN + col) = o1;
        }
    }
}

// ---------------- weight conversions ----------------
__global__ void cvt_bf16_kernel(const float* __restrict__ in, __nv_bfloat16* __restrict__ out) {
    const int i = blockIdx.x * blockDim.x + threadIdx.x;
    float4 v = ((const float4*)in)[i];
    __nv_bfloat162 a, b;
    a.x = __float2bfloat16(v.x); a.y = __float2bfloat16(v.y);
    b.x = __float2bfloat16(v.z); b.y = __float2bfloat16(v.w);
    ((__nv_bfloat162*)out)[2 * i] = a;
    ((__nv_bfloat162*)out)[2 * i + 1] = b;
}
__global__ void tf32_round_kernel(const float* __restrict__ in, float* __restrict__ out) {
    const int i = blockIdx.x * blockDim.x + threadIdx.x;
    float4 v = ((const float4*)in)[i];
    v.x = to_tf32(v.x); v.y = to_tf32(v.y); v.z = to_tf32(v.z); v.w = to_tf32(v.w);
    ((float4*)out)[i] = v;
}

// ---------------- LayerNorm -> bf16 ----------------
__global__ void ln_kernel(const float* __restrict__ x,
                          const float* __restrict__ gamma,
                          const float* __restrict__ beta,
                          __nv_bfloat16* __restrict__ out) {
    const int row = blockIdx.x;
    const int tid = threadIdx.x;
    const float* xr = x + (size_t)row * D_;

    float4 xv = ((const float4*)xr)[tid];
    float sum = xv.x + xv.y + xv.z + xv.w;
    float sq  = xv.x * xv.x + xv.y * xv.y + xv.z * xv.z + xv.w * xv.w;

    __shared__ float2 red[32];
    float2 v2 = make_float2(sum, sq);
    #pragma unroll
    for (int o = 16; o > 0; o >>= 1) {
        v2.x += __shfl_down_sync(0xffffffffu, v2.x, o);
        v2.y += __shfl_down_sync(0xffffffffu, v2.y, o);
    }
    if ((tid & 31) == 0) red[tid >> 5] = v2;
    __syncthreads();
    if (tid < 32) {
        float2 w = (tid < 8) ? red[tid] : make_float2(0.f, 0.f);
        #pragma unroll
        for (int o = 4; o > 0; o >>= 1) {
            w.x += __shfl_down_sync(0xffffffffu, w.x, o);
            w.y += __shfl_down_sync(0xffffffffu, w.y, o);
        }
        if (tid == 0) red[0] = w;
    }
    __syncthreads();
    const float mu  = red[0].x * (1.0f / D_);
    const float var = red[0].y * (1.0f / D_) - mu * mu;
    const float inv = rsqrtf(var + EPS_);

    float4 gm = ((const float4*)gamma)[tid];
    float4 b = ((const float4*)beta)[tid];
    __nv_bfloat162 p0, p1;
    p0.x = __float2bfloat16((xv.x - mu) * inv * gm.x + b.x);
    p0.y = __float2bfloat16((xv.y - mu) * inv * gm.y + b.y);
    p1.x = __float2bfloat16((xv.z - mu) * inv * gm.z + b.z);
    p1.y = __float2bfloat16((xv.w - mu) * inv * gm.w + b.w);
    __nv_bfloat162* op = (__nv_bfloat162*)(out + (size_t)row * D_);
    op[2 * tid] = p0;
    op[2 * tid + 1] = p1;
}

// ---------------- scores via bf16 mma: exp-rowsums over upper triangle ----------------
// grid (qt=16, bh=32), 256 threads (8 warps x 16 q-rows).
// smem: Q tile 16KB + 2 x K tile 16KB
#define SC_SMEMB (3 * 16384)

__device__ __forceinline__ void sc_load_tile(uint32_t dst, const __nv_bfloat16* src,
                                             int rowbase, int hh, int tid) {
    #pragma unroll
    for (int i = 0; i < 4; i++) {
        const int c = tid + i * 256;
        const int row = c >> 3;
        const int c4 = c & 7;
        const uint32_t off = (uint32_t)(row * 128 + ((c4 ^ (row & 7)) << 4));
        cp_async16(dst + off, src + (size_t)(rowbase + row) * D_ + hh * HD_ + c4 * 8);
    }
}

__global__ __launch_bounds__(256) void scores_mma(const __nv_bfloat16* __restrict__ Qb,
                                                  const __nv_bfloat16* __restrict__ Kb,
                                                  float* __restrict__ esum,
                                                  float* __restrict__ ediag) {
    extern __shared__ char sms[];
    const uint32_t sbase = smem_u32(sms);
    const uint32_t* su = (const uint32_t*)sms;
    const int tid = threadIdx.x;
    const int wid = tid >> 5, lane = tid & 31;
    const int g = lane >> 2, tg = lane & 3;
    const int qt = blockIdx.x;
    const int bh = blockIdx.y;
    const int b = bh >> 4, hh = bh & 15;
    const int q0 = qt * 128;

    // load Q tile + first K tile
    sc_load_tile(sbase, Qb, b * S_ + q0, hh, tid);
    sc_load_tile(sbase + 16384, Kb, b * S_ + q0, hh, tid);
    CP_COMMIT();
    asm volatile("cp.async.wait_group 0;" ::: "memory");
    __syncthreads();

    // A fragments (16 q-rows per warp), loaded once
    uint32_t af[4][4];
    const int r0 = q0 + wid * 16 + g;
    const int r1 = r0 + 8;
    {
        const int rowa = wid * 16 + g;
        #pragma unroll
        for (int ks = 0; ks < 4; ks++) {
            const int p0 = (ks * 8 + tg) ^ (g << 2);
            const int p1 = (ks * 8 + 4 + tg) ^ (g << 2);
            af[ks][0] = su[rowa * 32 + p0];
            af[ks][1] = su[(rowa + 8) * 32 + p0];
            af[ks][2] = su[rowa * 32 + p1];
            af[ks][3] = su[(rowa + 8) * 32 + p1];
        }
    }

    float racc0 = 0.f, racc1 = 0.f, ed0 = 0.f, ed1 = 0.f;
    const float scale = 0.03125f;

    for (int kt = qt; kt < 16; kt++) {
        const int buf = (kt - qt) & 1;
        if (kt + 1 < 16) {
            sc_load_tile(sbase + 16384 + (buf ^ 1) * 16384, Kb, b * S_ + (kt + 1) * 128, hh, tid);
            CP_COMMIT();
        }
        const uint32_t* ks_ = su + 4096 + buf * 4096;
        const int kbase = kt * 128;

        #pragma unroll 4
        for (int j = 0; j < 16; j++) {
            float c[4] = {0.f, 0.f, 0.f, 0.f};
            #pragma unroll
            for (int ksi = 0; ksi < 4; ksi++) {
                const int p0 = (ksi * 8 + tg) ^ (g << 2);
                const int p1 = (ksi * 8 + 4 + tg) ^ (g << 2);
                const int n = j * 8 + g;
                uint32_t bf[2];
                bf[0] = ks_[n * 32 + p0];
                bf[1] = ks_[n * 32 + p1];
                mma_bf16(c, af[ksi], bf);
            }
            const int col0 = kbase + j * 8 + tg * 2;
            const int col1 = col0 + 1;
            float e00 = (col0 >= r0) ? __expf(c[0] * scale) : 0.f;
            float e01 = (col1 >= r0) ? __expf(c[1] * scale) : 0.f;
            float e10 = (col0 >= r1) ? __expf(c[2] * scale) : 0.f;
            float e11 = (col1 >= r1) ? __expf(c[3] * scale) : 0.f;
            racc0 += e00 + e01;
            racc1 += e10 + e11;
            if (col0 == r0) ed0 = e00;
            if (col1 == r0) ed0 = e01;
            if (col0 == r1) ed1 = e10;
            if (col1 == r1) ed1 = e11;
        }
        if (kt + 1 < 16) asm volatile("cp.async.wait_group 0;" ::: "memory");
        __syncthreads();
    }

    // reduce over the 4 lanes sharing a row (tg group)
    #pragma unroll
    for (int o = 1; o <= 2; o <<= 1) {
        racc0 += __shfl_xor_sync(0xffffffffu, racc0, o);
        racc1 += __shfl_xor_sync(0xffffffffu, racc1, o);
        ed0   += __shfl_xor_sync(0xffffffffu, ed0, o);
        ed1   += __shfl_xor_sync(0xffffffffu, ed1, o);
    }
    if (tg == 0) {
        esum[bh * S_ + r0]  = (float)r0 + racc0;
        esum[bh * S_ + r1]  = (float)r1 + racc1;
        ediag[bh * S_ + r0] = ed0;
        ediag[bh * S_ + r1] = ed1;
    }
}

// ---------------- attention output: tile sums (64-row tiles) then prefix ----------------
__global__ __launch_bounds__(64) void tilesum_kernel(const float* __restrict__ V,
                                                     float* __restrict__ tsum) {
    const int t  = blockIdx.x;       // 0..31
    const int bh = blockIdx.y;       // 0..31
    const int b  = bh / H_;
    const int hh = bh % H_;
    const int d = threadIdx.x;

    const size_t base = ((size_t)b * S_) * D_ + hh * HD_ + d;
    const int s0 = t * 64;
    float s = 0.f;
    #pragma unroll 4
    for (int i = 0; i < 64; i++) s += V[base + (size_t)(s0 + i) * D_];
    tsum[(bh * 32 + t) * 64 + d] = s;
}

__global__ __launch_bounds__(64) void attnout_kernel(const float* __restrict__ V,
                                                     const float* __restrict__ tsum,
                                                     const float* __restrict__ esum,
                                                     const float* __restrict__ ediag,
                                                     float* __restrict__ out) {
    const int t  = blockIdx.x;   // 0..31
    const int bh = blockIdx.y;
    const int b  = bh / H_;
    const int hh = bh % H_;
    const int d = threadIdx.x;

    const size_t base = ((size_t)b * S_) * D_ + hh * HD_ + d;

    float run = 0.f;
    for (int tt = 0; tt < t; tt++) run += tsum[(bh * 32 + tt) * 64 + d];

    const int s0 = t * 64;
    #pragma unroll 4
    for (int i = 0; i < 64; i++) {
        const int q = s0 + i;
        const float val = V[base + (size_t)q * D_];
        const float e   = ediag[bh * S_ + q];
        const float Dn  = esum[bh * S_ + q];
        out[base + (size_t)q * D_] = to_tf32((run + e * val) / Dn);
        run += val;
    }
}

// ---------------- launch ----------------
extern "C" void kernel_launch(void* const* d_in, const int* in_sizes, int n_in,
                              void* d_out, int out_size) {
    const float* x     = (const float*)d_in[0];
    const float* wq    = (const float*)d_in[1];
    const float* bq    = (const float*)d_in[2];
    const float* wk    = (const float*)d_in[3];
    const float* bk    = (const float*)d_in[4];
    const float* wv    = (const float*)d_in[5];
    const float* bv    = (const float*)d_in[6];
    const float* wo    = (const float*)d_in[7];
    const float* bo    = (const float*)d_in[8];
    const float* gamma = (const float*)d_in[9];
    const float* beta  = (const float*)d_in[10];
    float* out = (float*)d_out;

    __nv_bfloat16 *hb, *qb, *kb, *wqb, *wkb, *wvb;
    float *vbuf, *cbuf, *esum, *ediag, *tsum, *wor;
    cudaGetSymbolAddress((void**)&hb,    g_hb);
    cudaGetSymbolAddress((void**)&qb,    g_qb);
    cudaGetSymbolAddress((void**)&kb,    g_kb);
    cudaGetSymbolAddress((void**)&vbuf,  g_v);
    cudaGetSymbolAddress((void**)&cbuf,  g_concat);
    cudaGetSymbolAddress((void**)&esum,  g_esum);
    cudaGetSymbolAddress((void**)&ediag, g_ediag);
    cudaGetSymbolAddress((void**)&tsum,  g_tsum);
    cudaGetSymbolAddress((void**)&wqb,   g_wqb);
    cudaGetSymbolAddress((void**)&wkb,   g_wkb);
    cudaGetSymbolAddress((void**)&wvb,   g_wvb);
    cudaGetSymbolAddress((void**)&wor,   g_wor);

    cudaFuncSetAttribute(gemm_mma, cudaFuncAttributeMaxDynamicSharedMemorySize, G_SMEMB);
    cudaFuncSetAttribute(gemm_bf16, cudaFuncAttributeMaxDynamicSharedMemorySize, BG_SMEMB);
    cudaFuncSetAttribute(scores_mma, cudaFuncAttributeMaxDynamicSharedMemorySize, SC_SMEMB);

    const int M = B_ * S_;  // 4096

    const int rblocks = (D_ * D_ / 4) / 256;  // 1024
    cvt_bf16_kernel<<<rblocks, 256>>>(wq, wqb);
    cvt_bf16_kernel<<<rblocks, 256>>>(wk, wkb);
    cvt_bf16_kernel<<<rblocks, 256>>>(wv, wvb);
    tf32_round_kernel<<<rblocks, 256>>>(wo, wor);

    ln_kernel<<<M, 256>>>(x, gamma, beta, hb);

    dim3 gg(D_ / 128, M / 128);  // (8, 32)
    gemm_bf16<<<gg, 256, BG_SMEMB>>>(hb, wqb, bq, qb, nullptr);
    gemm_bf16<<<gg, 256, BG_SMEMB>>>(hb, wkb, bk, kb, nullptr);
    gemm_bf16<<<gg, 256, BG_SMEMB>>>(hb, wvb, bv, nullptr, vbuf);

    dim3 gs(16, B_ * H_);
    scores_mma<<<gs, 256, SC_SMEMB>>>(qb, kb, esum, ediag);

    dim3 ga(32, B_ * H_);
    tilesum_kernel<<<ga, 64>>>(vbuf, tsum);
    attnout_kernel<<<ga, 64>>>(vbuf, tsum, esum, ediag, cbuf);

    gemm_mma<<<gg, 256, G_SMEMB>>>(cbuf, wor, bo, x, out);
}

// round 5
// speedup vs baseline: 6.4946x; 1.1487x over previous
#include <cuda_runtime.h>
#include <cuda_bf16.h>
#include <math.h>
#include <cstdint>

#define B_ 2
#define S_ 2048
#define D_ 1024
#define H_ 16
#define HD_ 64
#define EPS_ 1e-5f

// ---------------- scratch ----------------
__device__ __nv_bfloat16 g_hb[B_ * S_ * D_];    // layernorm out (bf16)
__device__ __nv_bfloat16 g_qb[B_ * S_ * D_];
__device__ __nv_bfloat16 g_kb[B_ * S_ * D_];
__device__ __nv_bfloat16 g_vb[B_ * S_ * D_];
__device__ __nv_bfloat16 g_cb[B_ * S_ * D_];    // concat (bf16)
__device__ float         g_esum[B_ * H_ * S_];
__device__ float         g_ediag[B_ * H_ * S_];
__device__ float         g_tsum[B_ * H_ * 64 * HD_];
__device__ __nv_bfloat16 g_wqb[D_ * D_];
__device__ __nv_bfloat16 g_wkb[D_ * D_];
__device__ __nv_bfloat16 g_wvb[D_ * D_];
__device__ __nv_bfloat16 g_wob[D_ * D_];

// ---------------- helpers ----------------
__device__ __forceinline__ uint32_t smem_u32(const void* p) {
    uint32_t a;
    asm("{ .reg .u64 t; cvta.to.shared.u64 t, %1; cvt.u32.u64 %0, t; }" : "=r"(a) : "l"(p));
    return a;
}
__device__ __forceinline__ void cp_async16(uint32_t dst, const void* src) {
    asm volatile("cp.async.cg.shared.global [%0], [%1], 16;" :: "r"(dst), "l"(src));
}
#define CP_COMMIT() asm volatile("cp.async.commit_group;" ::: "memory")

__device__ __forceinline__ void mma_bf16(float c[4], const uint32_t a[4], const uint32_t b[2]) {
    asm volatile(
        "mma.sync.aligned.m16n8k16.row.col.f32.bf16.bf16.f32 "
        "{%0,%1,%2,%3}, {%4,%5,%6,%7}, {%8,%9}, {%0,%1,%2,%3};"
        : "+f"(c[0]), "+f"(c[1]), "+f"(c[2]), "+f"(c[3])
        : "r"(a[0]), "r"(a[1]), "r"(a[2]), "r"(a[3]), "r"(b[0]), "r"(b[1]));
}

// ================= bf16 mma GEMM =================
// C[4096,1024] = A[4096,1024]bf16 @ W[1024,1024]bf16^T + bias (+res fp32)
// 128x128x64 tile, 3-stage cp.async, 8 warps. Stage: 128 rows * 64 bf16 = 16KB.
#define BG_STAGEB 16384
#define BG_SMEMB  (3 * BG_STAGEB * 2)   // 96 KB

__device__ __forceinline__ void bg_load_stage(uint32_t sbase, const __nv_bfloat16* A,
                                              const __nv_bfloat16* W,
                                              int bm, int bn, int it, int slot, int tid) {
    const int k0 = it * 64;
    const uint32_t abase = sbase + slot * BG_STAGEB;
    const uint32_t bbase = sbase + (3 + slot) * BG_STAGEB;
    #pragma unroll
    for (int i = 0; i < 4; i++) {
        const int c = tid + i * 256;  // 0..1023 chunk id
        const int row = c >> 3;
        const int c4 = c & 7;
        const uint32_t off = (uint32_t)(row * 128 + ((c4 ^ (row & 7)) << 4));
        cp_async16(abase + off, A + (size_t)(bm + row) * D_ + k0 + c4 * 8);
        cp_async16(bbase + off, W + (size_t)(bn + row) * D_ + k0 + c4 * 8);
    }
    CP_COMMIT();
}

__global__ __launch_bounds__(256, 2) void gemm_bf16(const __nv_bfloat16* __restrict__ A,
                                                    const __nv_bfloat16* __restrict__ W,
                                                    const float* __restrict__ bias,
                                                    __nv_bfloat16* __restrict__ Cb,
                                                    float* __restrict__ Cf,
                                                    const float* __restrict__ res) {
    extern __shared__ char smc[];
    const uint32_t sbase = smem_u32(smc);
    const uint32_t* su = (const uint32_t*)smc;   // bf16-pair view, row stride 32
    const int tid = threadIdx.x;
    const int wid = tid >> 5, lane = tid & 31;
    const int g = lane >> 2, tg = lane & 3;
    const int wm = (wid & 1) * 64, wn = (wid >> 1) * 32;
    const int bm = blockIdx.y * 128, bn = blockIdx.x * 128;

    float acc[4][4][4];
    #pragma unroll
    for (int i = 0; i < 4; i++)
        #pragma unroll
        for (int j = 0; j < 4; j++)
            #pragma unroll
            for (int e = 0; e < 4; e++) acc[i][j][e] = 0.f;

    bg_load_stage(sbase, A, W, bm, bn, 0, 0, tid);
    bg_load_stage(sbase, A, W, bm, bn, 1, 1, tid);

    const int nIter = D_ / 64;  // 16
    for (int it = 0; it < nIter; it++) {
        const int slot = it % 3;
        if (it < nIter - 1) {
            asm volatile("cp.async.wait_group 1;" ::: "memory");
        } else {
            asm volatile("cp.async.wait_group 0;" ::: "memory");
        }
        __syncthreads();
        if (it + 2 < nIter) bg_load_stage(sbase, A, W, bm, bn, it + 2, (it + 2) % 3, tid);

        const uint32_t* asu = su + slot * 4096;
        const uint32_t* bsu = su + (3 + slot) * 4096;

        #pragma unroll
        for (int ks = 0; ks < 4; ks++) {
            const int p0 = (ks * 8 + tg) ^ (g << 2);
            const int p1 = (ks * 8 + 4 + tg) ^ (g << 2);
            uint32_t af[4][4], bf[4][2];
            #pragma unroll
            for (int i = 0; i < 4; i++) {
                const int row = wm + i * 16 + g;
                af[i][0] = asu[row * 32 + p0];
                af[i][1] = asu[(row + 8) * 32 + p0];
                af[i][2] = asu[row * 32 + p1];
                af[i][3] = asu[(row + 8) * 32 + p1];
            }
            #pragma unroll
            for (int j = 0; j < 4; j++) {
                const int n = wn + j * 8 + g;
                bf[j][0] = bsu[n * 32 + p0];
                bf[j][1] = bsu[n * 32 + p1];
            }
            #pragma unroll
            for (int i = 0; i < 4; i++)
                #pragma unroll
                for (int j = 0; j < 4; j++) mma_bf16(acc[i][j], af[i], bf[j]);
        }
    }

    // epilogue
    #pragma unroll
    for (int i = 0; i < 4; i++) {
        const int row = bm + wm + i * 16 + g;
        #pragma unroll
        for (int j = 0; j < 4; j++) {
            const int col = bn + wn + j * 8 + tg * 2;
            const float2 bv = *(const float2*)(bias + col);
            float o00 = acc[i][j][0] + bv.x, o01 = acc[i][j][1] + bv.y;
            float o10 = acc[i][j][2] + bv.x, o11 = acc[i][j][3] + bv.y;
            if (res) {
                const float2 r0 = *(const float2*)(res + (size_t)row * D_ + col);
                const float2 r1 = *(const float2*)(res + (size_t)(row + 8) * D_ + col);
                o00 += r0.x; o01 += r0.y;
                o10 += r1.x; o11 += r1.y;
            }
            if (Cb) {
                __nv_bfloat162 h0, h1;
                h0.x = __float2bfloat16(o00); h0.y = __float2bfloat16(o01);
                h1.x = __float2bfloat16(o10); h1.y = __float2bfloat16(o11);
                *(__nv_bfloat162*)(Cb + (size_t)row * D_ + col) = h0;
                *(__nv_bfloat162*)(Cb + (size_t)(row + 8) * D_ + col) = h1;
            } else {
                *(float2*)(Cf + (size_t)row * D_ + col) = make_float2(o00, o01);
                *(float2*)(Cf + (size_t)(row + 8) * D_ + col) = make_float2(o10, o11);
            }
        }
    }
}

// ---------------- fused weight conversion (4 matrices) ----------------
__global__ void cvt_bf16x4_kernel(const float* __restrict__ w0, const float* __restrict__ w1,
                                  const float* __restrict__ w2, const float* __restrict__ w3,
                                  __nv_bfloat16* __restrict__ o0, __nv_bfloat16* __restrict__ o1,
                                  __nv_bfloat16* __restrict__ o2, __nv_bfloat16* __restrict__ o3) {
    const int m = blockIdx.x >> 10;                 // which matrix
    const int i = ((blockIdx.x & 1023) << 8) + threadIdx.x;  // float4 index
    const float* in = (m == 0) ? w0 : (m == 1) ? w1 : (m == 2) ? w2 : w3;
    __nv_bfloat16* out = (m == 0) ? o0 : (m == 1) ? o1 : (m == 2) ? o2 : o3;
    float4 v = ((const float4*)in)[i];
    __nv_bfloat162 a, b;
    a.x = __float2bfloat16(v.x); a.y = __float2bfloat16(v.y);
    b.x = __float2bfloat16(v.z); b.y = __float2bfloat16(v.w);
    ((__nv_bfloat162*)out)[2 * i] = a;
    ((__nv_bfloat162*)out)[2 * i + 1] = b;
}

// ---------------- LayerNorm -> bf16 ----------------
__global__ void ln_kernel(const float* __restrict__ x,
                          const float* __restrict__ gamma,
                          const float* __restrict__ beta,
                          __nv_bfloat16* __restrict__ out) {
    const int row = blockIdx.x;
    const int tid = threadIdx.x;
    const float* xr = x + (size_t)row * D_;

    float4 xv = ((const float4*)xr)[tid];
    float sum = xv.x + xv.y + xv.z + xv.w;
    float sq  = xv.x * xv.x + xv.y * xv.y + xv.z * xv.z + xv.w * xv.w;

    __shared__ float2 red[32];
    float2 v2 = make_float2(sum, sq);
    #pragma unroll
    for (int o = 16; o > 0; o >>= 1) {
        v2.x += __shfl_down_sync(0xffffffffu, v2.x, o);
        v2.y += __shfl_down_sync(0xffffffffu, v2.y, o);
    }
    if ((tid & 31) == 0) red[tid >> 5] = v2;
    __syncthreads();
    if (tid < 32) {
        float2 w = (tid < 8) ? red[tid] : make_float2(0.f, 0.f);
        #pragma unroll
        for (int o = 4; o > 0; o >>= 1) {
            w.x += __shfl_down_sync(0xffffffffu, w.x, o);
            w.y += __shfl_down_sync(0xffffffffu, w.y, o);
        }
        if (tid == 0) red[0] = w;
    }
    __syncthreads();
    const float mu  = red[0].x * (1.0f / D_);
    const float var = red[0].y * (1.0f / D_) - mu * mu;
    const float inv = rsqrtf(var + EPS_);

    float4 gm = ((const float4*)gamma)[tid];
    float4 b = ((const float4*)beta)[tid];
    __nv_bfloat162 p0, p1;
    p0.x = __float2bfloat16((xv.x - mu) * inv * gm.x + b.x);
    p0.y = __float2bfloat16((xv.y - mu) * inv * gm.y + b.y);
    p1.x = __float2bfloat16((xv.z - mu) * inv * gm.z + b.z);
    p1.y = __float2bfloat16((xv.w - mu) * inv * gm.w + b.w);
    __nv_bfloat162* op = (__nv_bfloat162*)(out + (size_t)row * D_);
    op[2 * tid] = p0;
    op[2 * tid + 1] = p1;
}

// ---------------- scores via bf16 mma ----------------
#define SC_SMEMB (3 * 16384)

__device__ __forceinline__ void sc_load_tile(uint32_t dst, const __nv_bfloat16* src,
                                             int rowbase, int hh, int tid) {
    #pragma unroll
    for (int i = 0; i < 4; i++) {
        const int c = tid + i * 256;
        const int row = c >> 3;
        const int c4 = c & 7;
        const uint32_t off = (uint32_t)(row * 128 + ((c4 ^ (row & 7)) << 4));
        cp_async16(dst + off, src + (size_t)(rowbase + row) * D_ + hh * HD_ + c4 * 8);
    }
}

__global__ __launch_bounds__(256) void scores_mma(const __nv_bfloat16* __restrict__ Qb,
                                                  const __nv_bfloat16* __restrict__ Kb,
                                                  float* __restrict__ esum,
                                                  float* __restrict__ ediag) {
    extern __shared__ char sms[];
    const uint32_t sbase = smem_u32(sms);
    const uint32_t* su = (const uint32_t*)sms;
    const int tid = threadIdx.x;
    const int wid = tid >> 5, lane = tid & 31;
    const int g = lane >> 2, tg = lane & 3;
    const int qt = blockIdx.x;
    const int bh = blockIdx.y;
    const int b = bh >> 4, hh = bh & 15;
    const int q0 = qt * 128;

    sc_load_tile(sbase, Qb, b * S_ + q0, hh, tid);
    sc_load_tile(sbase + 16384, Kb, b * S_ + q0, hh, tid);
    CP_COMMIT();
    asm volatile("cp.async.wait_group 0;" ::: "memory");
    __syncthreads();

    uint32_t af[4][4];
    const int r0 = q0 + wid * 16 + g;
    const int r1 = r0 + 8;
    {
        const int rowa = wid * 16 + g;
        #pragma unroll
        for (int ks = 0; ks < 4; ks++) {
            const int p0 = (ks * 8 + tg) ^ (g << 2);
            const int p1 = (ks * 8 + 4 + tg) ^ (g << 2);
            af[ks][0] = su[rowa * 32 + p0];
            af[ks][1] = su[(rowa + 8) * 32 + p0];
            af[ks][2] = su[rowa * 32 + p1];
            af[ks][3] = su[(rowa + 8) * 32 + p1];
        }
    }

    float racc0 = 0.f, racc1 = 0.f, ed0 = 0.f, ed1 = 0.f;
    const float scale = 0.03125f;

    for (int kt = qt; kt < 16; kt++) {
        const int buf = (kt - qt) & 1;
        if (kt + 1 < 16) {
            sc_load_tile(sbase + 16384 + (buf ^ 1) * 16384, Kb, b * S_ + (kt + 1) * 128, hh, tid);
            CP_COMMIT();
        }
        const uint32_t* ks_ = su + 4096 + buf * 4096;
        const int kbase = kt * 128;

        #pragma unroll 4
        for (int j = 0; j < 16; j++) {
            float c[4] = {0.f, 0.f, 0.f, 0.f};
            #pragma unroll
            for (int ksi = 0; ksi < 4; ksi++) {
                const int p0 = (ksi * 8 + tg) ^ (g << 2);
                const int p1 = (ksi * 8 + 4 + tg) ^ (g << 2);
                const int n = j * 8 + g;
                uint32_t bf[2];
                bf[0] = ks_[n * 32 + p0];
                bf[1] = ks_[n * 32 + p1];
                mma_bf16(c, af[ksi], bf);
            }
            const int col0 = kbase + j * 8 + tg * 2;
            const int col1 = col0 + 1;
            float e00 = (col0 >= r0) ? __expf(c[0] * scale) : 0.f;
            float e01 = (col1 >= r0) ? __expf(c[1] * scale) : 0.f;
            float e10 = (col0 >= r1) ? __expf(c[2] * scale) : 0.f;
            float e11 = (col1 >= r1) ? __expf(c[3] * scale) : 0.f;
            racc0 += e00 + e01;
            racc1 += e10 + e11;
            if (col0 == r0) ed0 = e00;
            if (col1 == r0) ed0 = e01;
            if (col0 == r1) ed1 = e10;
            if (col1 == r1) ed1 = e11;
        }
        if (kt + 1 < 16) asm volatile("cp.async.wait_group 0;" ::: "memory");
        __syncthreads();
    }

    #pragma unroll
    for (int o = 1; o <= 2; o <<= 1) {
        racc0 += __shfl_xor_sync(0xffffffffu, racc0, o);
        racc1 += __shfl_xor_sync(0xffffffffu, racc1, o);
        ed0   += __shfl_xor_sync(0xffffffffu, ed0, o);
        ed1   += __shfl_xor_sync(0xffffffffu, ed1, o);
    }
    if (tg == 0) {
        esum[bh * S_ + r0]  = (float)r0 + racc0;
        esum[bh * S_ + r1]  = (float)r1 + racc1;
        ediag[bh * S_ + r0] = ed0;
        ediag[bh * S_ + r1] = ed1;
    }
}

// ---------------- attention output: 32-row tile sums then prefix ----------------
__global__ __launch_bounds__(64) void tilesum_kernel(const __nv_bfloat16* __restrict__ V,
                                                     float* __restrict__ tsum) {
    const int t  = blockIdx.x;       // 0..63
    const int bh = blockIdx.y;       // 0..31
    const int b  = bh / H_;
    const int hh = bh % H_;
    const int d = threadIdx.x;

    const size_t base = ((size_t)b * S_) * D_ + hh * HD_ + d;
    const int s0 = t * 32;
    float s = 0.f;
    #pragma unroll 8
    for (int i = 0; i < 32; i++) s += __bfloat162float(V[base + (size_t)(s0 + i) * D_]);
    tsum[(bh * 64 + t) * 64 + d] = s;
}

__global__ __launch_bounds__(64) void attnout_kernel(const __nv_bfloat16* __restrict__ V,
                                                     const float* __restrict__ tsum,
                                                     const float* __restrict__ esum,
                                                     const float* __restrict__ ediag,
                                                     __nv_bfloat16* __restrict__ out) {
    const int t  = blockIdx.x;   // 0..63
    const int bh = blockIdx.y;
    const int b  = bh / H_;
    const int hh = bh % H_;
    const int d = threadIdx.x;

    const size_t base = ((size_t)b * S_) * D_ + hh * HD_ + d;

    float run = 0.f;
    #pragma unroll 8
    for (int tt = 0; tt < t; tt++) run += tsum[(bh * 64 + tt) * 64 + d];

    const int s0 = t * 32;
    #pragma unroll 8
    for (int i = 0; i < 32; i++) {
        const int q = s0 + i;
        const float val = __bfloat162float(V[base + (size_t)q * D_]);
        const float e   = ediag[bh * S_ + q];
        const float Dn  = esum[bh * S_ + q];
        out[base + (size_t)q * D_] = __float2bfloat16((run + e * val) / Dn);
        run += val;
    }
}

// ---------------- launch ----------------
extern "C" void kernel_launch(void* const* d_in, const int* in_sizes, int n_in,
                              void* d_out, int out_size) {
    const float* x     = (const float*)d_in[0];
    const float* wq    = (const float*)d_in[1];
    const float* bq    = (const float*)d_in[2];
    const float* wk    = (const float*)d_in[3];
    const float* bk    = (const float*)d_in[4];
    const float* wv    = (const float*)d_in[5];
    const float* bv    = (const float*)d_in[6];
    const float* wo    = (const float*)d_in[7];
    const float* bo    = (const float*)d_in[8];
    const float* gamma = (const float*)d_in[9];
    const float* beta  = (const float*)d_in[10];
    float* out = (float*)d_out;

    __nv_bfloat16 *hb, *qb, *kb, *vb, *cb, *wqb, *wkb, *wvb, *wob;
    float *esum, *ediag, *tsum;
    cudaGetSymbolAddress((void**)&hb,    g_hb);
    cudaGetSymbolAddress((void**)&qb,    g_qb);
    cudaGetSymbolAddress((void**)&kb,    g_kb);
    cudaGetSymbolAddress((void**)&vb,    g_vb);
    cudaGetSymbolAddress((void**)&cb,    g_cb);
    cudaGetSymbolAddress((void**)&esum,  g_esum);
    cudaGetSymbolAddress((void**)&ediag, g_ediag);
    cudaGetSymbolAddress((void**)&tsum,  g_tsum);
    cudaGetSymbolAddress((void**)&wqb,   g_wqb);
    cudaGetSymbolAddress((void**)&wkb,   g_wkb);
    cudaGetSymbolAddress((void**)&wvb,   g_wvb);
    cudaGetSymbolAddress((void**)&wob,   g_wob);

    cudaFuncSetAttribute(gemm_bf16, cudaFuncAttributeMaxDynamicSharedMemorySize, BG_SMEMB);
    cudaFuncSetAttribute(scores_mma, cudaFuncAttributeMaxDynamicSharedMemorySize, SC_SMEMB);

    const int M = B_ * S_;  // 4096

    cvt_bf16x4_kernel<<<4096, 256>>>(wq, wk, wv, wo, wqb, wkb, wvb, wob);

    ln_kernel<<<M, 256>>>(x, gamma, beta, hb);

    dim3 gg(D_ / 128, M / 128);  // (8, 32)
    gemm_bf16<<<gg, 256, BG_SMEMB>>>(hb, wqb, bq, qb, nullptr, nullptr);
    gemm_bf16<<<gg, 256, BG_SMEMB>>>(hb, wkb, bk, kb, nullptr, nullptr);
    gemm_bf16<<<gg, 256, BG_SMEMB>>>(hb, wvb, bv, vb, nullptr, nullptr);

    dim3 gs(16, B_ * H_);
    scores_mma<<<gs, 256, SC_SMEMB>>>(qb, kb, esum, ediag);

    dim3 ga(64, B_ * H_);
    tilesum_kernel<<<ga, 64>>>(vb, tsum);
    attnout_kernel<<<ga, 64>>>(vb, tsum, esum, ediag, cb);

    gemm_bf16<<<gg, 256, BG_SMEMB>>>(cb, wob, bo, nullptr, out, x);
}